// round 10
// baseline (speedup 1.0000x reference)
#include <cuda_runtime.h>
#include <cuda_bf16.h>
#include <cstdint>

// ---------------------------------------------------------------------------
// AttentionIn via legacy mma.sync tf32 + ldmatrix (sm_103 base target)
// out = concat(residual, q, k, v); q/k rotary on first 64 dims/head, v plain
// Pre-rounded operands (rna->tf32); W pre-transposed K-major; LDSM fragment loads.
// ---------------------------------------------------------------------------

#define TOKENS   8192
#define DMODEL   2048
#define NTOT     6144            // 3 mats * 16 heads * 128
#define DHEAD    128
#define SEQLEN   2048
#define ROT_DIM  64

#define BM 128
#define BN 128
#define BK 32
#define LDT 36                   // smem row stride (floats): conflict-free for LDSM
#define A_F (BM * LDT)           // 4608 floats
#define B_F (BN * LDT)           // 4608 floats
#define STAGE_F (A_F + B_F)      // 9216 floats
#define SMEM_BYTES (2 * STAGE_F * 4)   // 73728 bytes

// scratch (module-static device memory; no runtime allocation)
__device__ float  g_xr[TOKENS * DMODEL];        // rna(tf32)-rounded x
__device__ float  g_wt[(size_t)NTOT * DMODEL];  // W K-major [n][k], rounded
__device__ float2 g_sincos[SEQLEN * 32];        // [pos][pair] -> (sin, cos)

// ---------------------------------------------------------------------------
__device__ __forceinline__ uint32_t f2tf32(float f) {
    uint32_t r;
    asm("cvt.rna.tf32.f32 %0, %1;" : "=r"(r) : "f"(f));
    return r;
}
__device__ __forceinline__ void cp_async16(void* smem_ptr, const void* gmem_ptr) {
    unsigned s = (unsigned)__cvta_generic_to_shared(smem_ptr);
    asm volatile("cp.async.cg.shared.global [%0], [%1], 16;\n" :: "r"(s), "l"(gmem_ptr));
}
__device__ __forceinline__ void cp_commit() {
    asm volatile("cp.async.commit_group;\n");
}
template <int N>
__device__ __forceinline__ void cp_wait() {
    asm volatile("cp.async.wait_group %0;\n" :: "n"(N));
}
__device__ __forceinline__ void ldsm_x4(uint32_t (&r)[4], uint32_t saddr) {
    asm volatile("ldmatrix.sync.aligned.m8n8.x4.shared.b16 {%0,%1,%2,%3}, [%4];"
                 : "=r"(r[0]), "=r"(r[1]), "=r"(r[2]), "=r"(r[3]) : "r"(saddr));
}
__device__ __forceinline__ void mma_tf32(float (&d)[4], const uint32_t a0,
                                         const uint32_t a1, const uint32_t a2,
                                         const uint32_t a3, const uint32_t b0,
                                         const uint32_t b1) {
    asm volatile(
        "mma.sync.aligned.m16n8k8.row.col.f32.tf32.tf32.f32 "
        "{%0,%1,%2,%3}, {%4,%5,%6,%7}, {%8,%9}, {%0,%1,%2,%3};"
        : "+f"(d[0]), "+f"(d[1]), "+f"(d[2]), "+f"(d[3])
        : "r"(a0), "r"(a1), "r"(a2), "r"(a3), "r"(b0), "r"(b1));
}

// ---------------------------------------------------------------------------
// prep kernels
// ---------------------------------------------------------------------------
__global__ void sincos_kernel() {
    int idx = blockIdx.x * blockDim.x + threadIdx.x;   // 65536
    int pos = idx >> 5, i = idx & 31;
    float freq = powf(10000.0f, (float)i * (1.0f / 32.0f));
    float ang  = (float)pos / freq;
    g_sincos[idx] = make_float2(sinf(ang), cosf(ang));
}

__global__ void copy_kernel(float4* __restrict__ dst, const float4* __restrict__ src, int n) {
    int i = blockIdx.x * blockDim.x + threadIdx.x;
    int stride = gridDim.x * blockDim.x;
    for (; i < n; i += stride) dst[i] = src[i];
}

__global__ void roundx_kernel(const float4* __restrict__ x, int n) {
    float4* dst = reinterpret_cast<float4*>(g_xr);
    int i = blockIdx.x * blockDim.x + threadIdx.x;
    int stride = gridDim.x * blockDim.x;
    for (; i < n; i += stride) {
        float4 v = x[i];
        v.x = __uint_as_float(f2tf32(v.x));
        v.y = __uint_as_float(f2tf32(v.y));
        v.z = __uint_as_float(f2tf32(v.z));
        v.w = __uint_as_float(f2tf32(v.w));
        dst[i] = v;
    }
}

// W[mat][head][k][nin] -> g_wt[(mat*16+head)*128 + nin][k], rna-rounded
__global__ void wprep_kernel(const float* __restrict__ WQ,
                             const float* __restrict__ WK,
                             const float* __restrict__ WV) {
    __shared__ float t[32][33];
    int n0 = blockIdx.x * 32;     // 192 tiles over n
    int k0 = blockIdx.y * 32;     // 64 tiles over k
    int tx = threadIdx.x, ty = threadIdx.y;   // 32 x 8
#pragma unroll
    for (int j = 0; j < 4; j++) {
        int n = n0 + tx;
        int k = k0 + ty + j * 8;
        int mat = n >> 11;
        int rest = n & 2047;                 // head*128 + nin
        const float* W = (mat == 0) ? WQ : (mat == 1) ? WK : WV;
        float v = W[(size_t)(rest >> 7) * DMODEL * DHEAD + (size_t)k * DHEAD + (rest & 127)];
        t[ty + j * 8][tx] = __uint_as_float(f2tf32(v));
    }
    __syncthreads();
#pragma unroll
    for (int j = 0; j < 4; j++) {
        int n = n0 + ty + j * 8;
        int k = k0 + tx;
        g_wt[(size_t)n * DMODEL + k] = t[tx][ty + j * 8];
    }
}

// ---------------------------------------------------------------------------
// GEMM: gridDim = (48 [mat*16+head], 64 [M tiles]), 256 threads, 8 warps (4m x 2n)
// ---------------------------------------------------------------------------
__global__ void __launch_bounds__(256, 2)
qkv_gemm_kernel(const float* __restrict__ bQ, const float* __restrict__ bK,
                const float* __restrict__ bV, float* __restrict__ out) {
    extern __shared__ float smem[];

    const int nb   = blockIdx.x;           // 0..47
    const int mb   = blockIdx.y;           // 0..63
    const int mat  = nb >> 4;              // 0=Q, 1=K, 2=V
    const int head = nb & 15;

    const float* Ag = g_xr + (size_t)mb * BM * DMODEL;
    const float* Bg = g_wt + (size_t)nb * BN * DMODEL;    // K-major [128 n][2048 k]
    const float* bsel = (mat == 0) ? bQ : (mat == 1) ? bK : bV;
    const float* bias = bsel + head * DHEAD;
    float* Og = out + (size_t)(mat + 1) * TOKENS * DMODEL + head * DHEAD;

    const bool do_rot = (mat < 2);         // rotary on Q/K only

    const int tid    = threadIdx.x;
    const int wid    = tid >> 5;
    const int lane   = tid & 31;
    const int warp_m = wid >> 1;           // 0..3 -> m offset *32
    const int warp_n = wid & 1;            // 0..1 -> n offset *64
    const int g      = lane >> 2;          // groupID
    const int c      = lane & 3;           // threadID_in_group

    float acc[2][8][4];
#pragma unroll
    for (int mi = 0; mi < 2; mi++)
#pragma unroll
        for (int ni = 0; ni < 8; ni++)
#pragma unroll
            for (int r = 0; r < 4; r++) acc[mi][ni][r] = 0.0f;

    // ---- LDSM per-thread base addresses (bytes, shared window) ----
    const uint32_t smem_u32 = (uint32_t)__cvta_generic_to_shared(smem);
    // A matrices: row = mbase + (lane&15), b32-col = (lane>>4)*4
    uint32_t a_addr[2];
#pragma unroll
    for (int mi = 0; mi < 2; mi++) {
        int row = warp_m * 32 + mi * 16 + (lane & 15);
        int col = (lane >> 4) * 4;
        a_addr[mi] = smem_u32 + (uint32_t)(row * LDT + col) * 4u;
    }
    // B matrices (pair p covers ni=2p,2p+1):
    // row = nbase + 16p + ((lane&16)>>1) + (lane&7), b32-col = ((lane>>3)&1)*4
    uint32_t b_addr[4];
#pragma unroll
    for (int p = 0; p < 4; p++) {
        int row = warp_n * 64 + p * 16 + ((lane & 16) >> 1) + (lane & 7);
        int col = ((lane >> 3) & 1) * 4;
        b_addr[p] = smem_u32 + (uint32_t)(A_F + row * LDT + col) * 4u;
    }

    // ---- stage loader: both tiles are [128 rows][32 k], stride LDT=36 ----
    auto load_stage = [&](int buf, int k0) {
        float* As = smem + buf * STAGE_F;
        float* Bs = As + A_F;
#pragma unroll
        for (int i = 0; i < 4; i++) {          // A: 1024 x 16B segs
            int id = tid + i * 256;
            int r = id >> 3, s = id & 7;
            cp_async16(As + r * LDT + s * 4, Ag + (size_t)r * DMODEL + k0 + s * 4);
        }
#pragma unroll
        for (int i = 0; i < 4; i++) {          // B: 1024 x 16B segs
            int id = tid + i * 256;
            int r = id >> 3, s = id & 7;
            cp_async16(Bs + r * LDT + s * 4, Bg + (size_t)r * DMODEL + k0 + s * 4);
        }
        cp_commit();
    };

    const int KT = DMODEL / BK;   // 64
    load_stage(0, 0);

    for (int kt = 0; kt < KT; kt++) {
        if (kt + 1 < KT) {
            load_stage((kt + 1) & 1, (kt + 1) * BK);
            cp_wait<1>();
        } else {
            cp_wait<0>();
        }
        __syncthreads();

        const uint32_t bufoff = (uint32_t)(kt & 1) * (STAGE_F * 4u);

#pragma unroll
        for (int ks = 0; ks < 4; ks++) {
            const uint32_t ksoff = bufoff + (uint32_t)ks * 32u;   // 8 b32 cols = 32B
            uint32_t a[2][4];
            ldsm_x4(a[0], a_addr[0] + ksoff);
            ldsm_x4(a[1], a_addr[1] + ksoff);
            uint32_t b[4][4];
#pragma unroll
            for (int p = 0; p < 4; p++) ldsm_x4(b[p], b_addr[p] + ksoff);

#pragma unroll
            for (int mi = 0; mi < 2; mi++)
#pragma unroll
                for (int p = 0; p < 4; p++) {
                    mma_tf32(acc[mi][2 * p],     a[mi][0], a[mi][1], a[mi][2], a[mi][3],
                             b[p][0], b[p][1]);
                    mma_tf32(acc[mi][2 * p + 1], a[mi][0], a[mi][1], a[mi][2], a[mi][3],
                             b[p][2], b[p][3]);
                }
        }
        __syncthreads();
    }

    // ---- epilogue: bias + rotary(Q,K only) + store ----
#pragma unroll
    for (int mi = 0; mi < 2; mi++) {
#pragma unroll
        for (int half = 0; half < 2; half++) {   // rows g / g+8
            int row = mb * BM + warp_m * 32 + mi * 16 + g + half * 8;  // token
            int pos = row & (SEQLEN - 1);
            float* orow = Og + (size_t)row * DMODEL;
            const float2* sct = g_sincos + pos * 32;
            int r0 = half * 2;   // acc regs {0,1} or {2,3}
#pragma unroll
            for (int ni = 0; ni < 8; ni++) {
                int e = warp_n * 64 + ni * 8 + c * 2;   // even column in head
                float v0 = acc[mi][ni][r0]     + bias[e];
                float v1 = acc[mi][ni][r0 + 1] + bias[e + 1];
                if (do_rot && e < ROT_DIM) {
                    float2 sc = sct[e >> 1];   // x=sin, y=cos
                    float o0 = v0 * sc.y - v1 * sc.x;
                    float o1 = v1 * sc.y + v0 * sc.x;
                    v0 = o0; v1 = o1;
                }
                *reinterpret_cast<float2*>(orow + e) = make_float2(v0, v1);
            }
        }
    }
}

// ---------------------------------------------------------------------------
extern "C" void kernel_launch(void* const* d_in, const int* in_sizes, int n_in,
                              void* d_out, int out_size) {
    const float* residual = (const float*)d_in[0];
    const float* x        = (const float*)d_in[1];
    const float* WQ       = (const float*)d_in[2];
    const float* WK       = (const float*)d_in[3];
    const float* WV       = (const float*)d_in[4];
    const float* bQ       = (const float*)d_in[5];
    const float* bK       = (const float*)d_in[6];
    const float* bV       = (const float*)d_in[7];
    float* out = (float*)d_out;

    // residual passthrough: 4,194,304 float4
    copy_kernel<<<4096, 256>>>((float4*)out, (const float4*)residual,
                               (TOKENS * DMODEL) / 4);
    // prep: rna-rounded x, transposed+rounded W (K-major), rotary table
    roundx_kernel<<<4096, 256>>>((const float4*)x, (TOKENS * DMODEL) / 4);
    wprep_kernel<<<dim3(NTOT / 32, DMODEL / 32), dim3(32, 8)>>>(WQ, WK, WV);
    sincos_kernel<<<256, 256>>>();

    // fused QKV GEMM + bias + rotary
    cudaFuncSetAttribute(qkv_gemm_kernel,
                         cudaFuncAttributeMaxDynamicSharedMemorySize, SMEM_BYTES);
    dim3 grid(48, 64);
    qkv_gemm_kernel<<<grid, 256, SMEM_BYTES>>>(bQ, bK, bV, out);
}

// round 13
// speedup vs baseline: 2.1590x; 2.1590x over previous
#include <cuda_runtime.h>
#include <cuda_fp16.h>
#include <cstdint>

// ---------------------------------------------------------------------------
// AttentionIn via legacy mma.sync fp16 (f32 accumulate), sm_103 base target
// out = concat(residual, q, k, v); q/k rotary on first 64 dims/head, v plain
// x/W pre-converted to fp16 (10-bit mantissa == tf32 precision, 2x rate).
// ---------------------------------------------------------------------------

#define TOKENS   8192
#define DMODEL   2048
#define NTOT     6144            // 3 mats * 16 heads * 128
#define DHEAD    128
#define SEQLEN   2048
#define ROT_DIM  64

#define BM 128
#define BN 128
#define BK 32
#define LDH 40                   // smem row stride in halfs (20 words): conflict-free
#define A_H (BM * LDH)           // 5120 halfs
#define B_H (BN * LDH)           // 5120 halfs
#define STAGE_H (A_H + B_H)      // 10240 halfs = 20480 B
#define SMEM_BYTES (2 * STAGE_H * 2)   // 40960 B

// scratch (module-static device memory; no runtime allocation)
__device__ __half  g_xh[TOKENS * DMODEL];        // fp16 x
__device__ __half  g_wh[(size_t)NTOT * DMODEL];  // fp16 W, K-major [n][k]
__device__ float2  g_sincos[SEQLEN * 32];        // [pos][pair] -> (sin, cos)

// ---------------------------------------------------------------------------
__device__ __forceinline__ void cp_async16(void* smem_ptr, const void* gmem_ptr) {
    unsigned s = (unsigned)__cvta_generic_to_shared(smem_ptr);
    asm volatile("cp.async.cg.shared.global [%0], [%1], 16;\n" :: "r"(s), "l"(gmem_ptr));
}
__device__ __forceinline__ void cp_commit() {
    asm volatile("cp.async.commit_group;\n");
}
template <int N>
__device__ __forceinline__ void cp_wait() {
    asm volatile("cp.async.wait_group %0;\n" :: "n"(N));
}
__device__ __forceinline__ uint32_t h2_bits(__half2 h) {
    uint32_t u;
    __builtin_memcpy(&u, &h, sizeof(u));
    return u;
}
__device__ __forceinline__ void mma_f16(float (&d)[4], const uint32_t a0,
                                        const uint32_t a1, const uint32_t a2,
                                        const uint32_t a3, const uint32_t b0,
                                        const uint32_t b1) {
    asm volatile(
        "mma.sync.aligned.m16n8k16.row.col.f32.f16.f16.f32 "
        "{%0,%1,%2,%3}, {%4,%5,%6,%7}, {%8,%9}, {%0,%1,%2,%3};"
        : "+f"(d[0]), "+f"(d[1]), "+f"(d[2]), "+f"(d[3])
        : "r"(a0), "r"(a1), "r"(a2), "r"(a3), "r"(b0), "r"(b1));
}

// ---------------------------------------------------------------------------
// prep kernels
// ---------------------------------------------------------------------------
__global__ void sincos_kernel() {
    int idx = blockIdx.x * blockDim.x + threadIdx.x;   // 65536
    int pos = idx >> 5, i = idx & 31;
    float freq = powf(10000.0f, (float)i * (1.0f / 32.0f));
    float ang  = (float)pos / freq;
    g_sincos[idx] = make_float2(sinf(ang), cosf(ang));
}

__global__ void copy_kernel(float4* __restrict__ dst, const float4* __restrict__ src, int n) {
    int i = blockIdx.x * blockDim.x + threadIdx.x;
    int stride = gridDim.x * blockDim.x;
    for (; i < n; i += stride) dst[i] = src[i];
}

// x (f32) -> g_xh (fp16); n = TOKENS*DMODEL/4
__global__ void cvtx_kernel(const float4* __restrict__ x, int n) {
    uint2* dst = reinterpret_cast<uint2*>(g_xh);
    int i = blockIdx.x * blockDim.x + threadIdx.x;
    int stride = gridDim.x * blockDim.x;
    for (; i < n; i += stride) {
        float4 v = x[i];
        __half2 h0 = __floats2half2_rn(v.x, v.y);
        __half2 h1 = __floats2half2_rn(v.z, v.w);
        dst[i] = make_uint2(h2_bits(h0), h2_bits(h1));
    }
}

// W[mat][head][k][nin] -> g_wh[(mat*16+head)*128 + nin][k], fp16
__global__ void wprep_kernel(const float* __restrict__ WQ,
                             const float* __restrict__ WK,
                             const float* __restrict__ WV) {
    __shared__ float t[32][33];
    int n0 = blockIdx.x * 32;     // 192 tiles over n
    int k0 = blockIdx.y * 32;     // 64 tiles over k
    int tx = threadIdx.x, ty = threadIdx.y;   // 32 x 8
#pragma unroll
    for (int j = 0; j < 4; j++) {
        int n = n0 + tx;
        int k = k0 + ty + j * 8;
        int mat = n >> 11;
        int rest = n & 2047;                 // head*128 + nin
        const float* W = (mat == 0) ? WQ : (mat == 1) ? WK : WV;
        t[ty + j * 8][tx] =
            W[(size_t)(rest >> 7) * DMODEL * DHEAD + (size_t)k * DHEAD + (rest & 127)];
    }
    __syncthreads();
#pragma unroll
    for (int j = 0; j < 4; j++) {
        int n = n0 + ty + j * 8;
        int k = k0 + tx;
        g_wh[(size_t)n * DMODEL + k] = __float2half_rn(t[tx][ty + j * 8]);
    }
}

// ---------------------------------------------------------------------------
// GEMM: gridDim = (48 [mat*16+head], 64 [M tiles]), 256 threads, 8 warps (4m x 2n)
// ---------------------------------------------------------------------------
__global__ void __launch_bounds__(256, 2)
qkv_gemm_kernel(const float* __restrict__ bQ, const float* __restrict__ bK,
                const float* __restrict__ bV, float* __restrict__ out) {
    extern __shared__ __half smem[];

    const int nb   = blockIdx.x;           // 0..47
    const int mb   = blockIdx.y;           // 0..63
    const int mat  = nb >> 4;              // 0=Q, 1=K, 2=V
    const int head = nb & 15;

    const __half* Ag = g_xh + (size_t)mb * BM * DMODEL;
    const __half* Bg = g_wh + (size_t)nb * BN * DMODEL;   // K-major [128 n][2048 k]
    const float* bsel = (mat == 0) ? bQ : (mat == 1) ? bK : bV;
    const float* bias = bsel + head * DHEAD;
    float* Og = out + (size_t)(mat + 1) * TOKENS * DMODEL + head * DHEAD;

    const bool do_rot = (mat < 2);         // rotary on Q/K only

    const int tid    = threadIdx.x;
    const int wid    = tid >> 5;
    const int lane   = tid & 31;
    const int warp_m = wid >> 1;           // 0..3 -> m offset *32
    const int warp_n = wid & 1;            // 0..1 -> n offset *64
    const int g      = lane >> 2;          // groupID
    const int c      = lane & 3;           // threadID_in_group

    float acc[2][8][4];
#pragma unroll
    for (int mi = 0; mi < 2; mi++)
#pragma unroll
        for (int ni = 0; ni < 8; ni++)
#pragma unroll
            for (int r = 0; r < 4; r++) acc[mi][ni][r] = 0.0f;

    // ---- stage loader: both tiles [128 rows][32 k] fp16, stride LDH=40 ----
    // per tile: 128 rows x 4 x 16B segs = 512 segs; 256 threads -> 2 iters
    auto load_stage = [&](int buf, int k0) {
        __half* As = smem + buf * STAGE_H;
        __half* Bs = As + A_H;
#pragma unroll
        for (int i = 0; i < 2; i++) {          // A
            int id = tid + i * 256;
            int r = id >> 2, s = id & 3;
            cp_async16(As + r * LDH + s * 8, Ag + (size_t)r * DMODEL + k0 + s * 8);
        }
#pragma unroll
        for (int i = 0; i < 2; i++) {          // B
            int id = tid + i * 256;
            int r = id >> 2, s = id & 3;
            cp_async16(Bs + r * LDH + s * 8, Bg + (size_t)r * DMODEL + k0 + s * 8);
        }
        cp_commit();
    };

    const int KT = DMODEL / BK;   // 64
    load_stage(0, 0);

    for (int kt = 0; kt < KT; kt++) {
        if (kt + 1 < KT) {
            load_stage((kt + 1) & 1, (kt + 1) * BK);
            cp_wait<1>();
        } else {
            cp_wait<0>();
        }
        __syncthreads();

        // word view: row stride 20 uint32 (LDH/2)
        const uint32_t* Aw = reinterpret_cast<const uint32_t*>(smem + (kt & 1) * STAGE_H);
        const uint32_t* Bw = Aw + A_H / 2;

#pragma unroll
        for (int ks = 0; ks < 2; ks++) {       // two k16 steps per BK=32
            const int kw = ks * 8;             // 8 words = 16 halfs
            uint32_t a[2][4];
#pragma unroll
            for (int mi = 0; mi < 2; mi++) {
                int r0 = warp_m * 32 + mi * 16 + g;
                a[mi][0] = Aw[r0 * 20 + kw + c];
                a[mi][1] = Aw[(r0 + 8) * 20 + kw + c];
                a[mi][2] = Aw[r0 * 20 + kw + c + 4];
                a[mi][3] = Aw[(r0 + 8) * 20 + kw + c + 4];
            }
            uint32_t b[8][2];
#pragma unroll
            for (int ni = 0; ni < 8; ni++) {
                int n = warp_n * 64 + ni * 8 + g;       // B row (K-major)
                b[ni][0] = Bw[n * 20 + kw + c];
                b[ni][1] = Bw[n * 20 + kw + c + 4];
            }
#pragma unroll
            for (int mi = 0; mi < 2; mi++)
#pragma unroll
                for (int ni = 0; ni < 8; ni++)
                    mma_f16(acc[mi][ni], a[mi][0], a[mi][1], a[mi][2], a[mi][3],
                            b[ni][0], b[ni][1]);
        }
        __syncthreads();
    }

    // ---- epilogue: bias + rotary(Q,K only) + store ----
#pragma unroll
    for (int mi = 0; mi < 2; mi++) {
#pragma unroll
        for (int half = 0; half < 2; half++) {   // rows g / g+8
            int row = mb * BM + warp_m * 32 + mi * 16 + g + half * 8;  // token
            int pos = row & (SEQLEN - 1);
            float* orow = Og + (size_t)row * DMODEL;
            const float2* sct = g_sincos + pos * 32;
            int r0 = half * 2;   // acc regs {0,1} or {2,3}
#pragma unroll
            for (int ni = 0; ni < 8; ni++) {
                int e = warp_n * 64 + ni * 8 + c * 2;   // even column in head
                float v0 = acc[mi][ni][r0]     + bias[e];
                float v1 = acc[mi][ni][r0 + 1] + bias[e + 1];
                if (do_rot && e < ROT_DIM) {
                    float2 sc = sct[e >> 1];   // x=sin, y=cos
                    float o0 = v0 * sc.y - v1 * sc.x;
                    float o1 = v1 * sc.y + v0 * sc.x;
                    v0 = o0; v1 = o1;
                }
                *reinterpret_cast<float2*>(orow + e) = make_float2(v0, v1);
            }
        }
    }
}

// ---------------------------------------------------------------------------
extern "C" void kernel_launch(void* const* d_in, const int* in_sizes, int n_in,
                              void* d_out, int out_size) {
    const float* residual = (const float*)d_in[0];
    const float* x        = (const float*)d_in[1];
    const float* WQ       = (const float*)d_in[2];
    const float* WK       = (const float*)d_in[3];
    const float* WV       = (const float*)d_in[4];
    const float* bQ       = (const float*)d_in[5];
    const float* bK       = (const float*)d_in[6];
    const float* bV       = (const float*)d_in[7];
    float* out = (float*)d_out;

    // residual passthrough: 4,194,304 float4
    copy_kernel<<<4096, 256>>>((float4*)out, (const float4*)residual,
                               (TOKENS * DMODEL) / 4);
    // prep: fp16 x, transposed fp16 W (K-major), rotary table
    cvtx_kernel<<<4096, 256>>>((const float4*)x, (TOKENS * DMODEL) / 4);
    wprep_kernel<<<dim3(NTOT / 32, DMODEL / 32), dim3(32, 8)>>>(WQ, WK, WV);
    sincos_kernel<<<256, 256>>>();

    // fused QKV GEMM + bias + rotary
    cudaFuncSetAttribute(qkv_gemm_kernel,
                         cudaFuncAttributeMaxDynamicSharedMemorySize, SMEM_BYTES);
    dim3 grid(48, 64);
    qkv_gemm_kernel<<<grid, 256, SMEM_BYTES>>>(bQ, bK, bV, out);
}

// round 15
// speedup vs baseline: 2.5777x; 1.1939x over previous
#include <cuda_runtime.h>
#include <cuda_fp16.h>
#include <cstdint>

// ---------------------------------------------------------------------------
// AttentionIn via legacy mma.sync fp16 (f32 accumulate), sm_103 base target
// out = concat(residual, q, k, v); q/k rotary on first 64 dims/head, v plain
// fp16 operands (10-bit mantissa == tf32 precision, 2x legacy tensor rate).
// BK=64, 3-stage cp.async ring, one barrier per K-step.
// ---------------------------------------------------------------------------

#define TOKENS   8192
#define DMODEL   2048
#define NTOT     6144            // 3 mats * 16 heads * 128
#define DHEAD    128
#define SEQLEN   2048
#define ROT_DIM  64

#define BM 128
#define BN 128
#define BK 64
#define NSTAGE 3
#define LDH 72                   // smem row stride in halfs (36 words): conflict-free
#define A_H (BM * LDH)           // 9216 halfs
#define B_H (BN * LDH)           // 9216 halfs
#define STAGE_H (A_H + B_H)      // 18432 halfs = 36864 B
#define SMEM_BYTES (NSTAGE * STAGE_H * 2)   // 110592 B

// scratch (module-static device memory; no runtime allocation)
__device__ __half  g_xh[TOKENS * DMODEL];        // fp16 x
__device__ __half  g_wh[(size_t)NTOT * DMODEL];  // fp16 W, K-major [n][k]
__device__ float2  g_sincos[SEQLEN * 32];        // [pos][pair] -> (sin, cos)

// ---------------------------------------------------------------------------
__device__ __forceinline__ void cp_async16(void* smem_ptr, const void* gmem_ptr) {
    unsigned s = (unsigned)__cvta_generic_to_shared(smem_ptr);
    asm volatile("cp.async.cg.shared.global [%0], [%1], 16;\n" :: "r"(s), "l"(gmem_ptr));
}
__device__ __forceinline__ void cp_commit() {
    asm volatile("cp.async.commit_group;\n");
}
template <int N>
__device__ __forceinline__ void cp_wait() {
    asm volatile("cp.async.wait_group %0;\n" :: "n"(N));
}
__device__ __forceinline__ uint32_t h2_bits(__half2 h) {
    uint32_t u;
    __builtin_memcpy(&u, &h, sizeof(u));
    return u;
}
__device__ __forceinline__ void mma_f16(float (&d)[4], const uint32_t a0,
                                        const uint32_t a1, const uint32_t a2,
                                        const uint32_t a3, const uint32_t b0,
                                        const uint32_t b1) {
    asm volatile(
        "mma.sync.aligned.m16n8k16.row.col.f32.f16.f16.f32 "
        "{%0,%1,%2,%3}, {%4,%5,%6,%7}, {%8,%9}, {%0,%1,%2,%3};"
        : "+f"(d[0]), "+f"(d[1]), "+f"(d[2]), "+f"(d[3])
        : "r"(a0), "r"(a1), "r"(a2), "r"(a3), "r"(b0), "r"(b1));
}

// ---------------------------------------------------------------------------
// prep kernels
// ---------------------------------------------------------------------------
__global__ void sincos_kernel() {
    int idx = blockIdx.x * blockDim.x + threadIdx.x;   // 65536
    int pos = idx >> 5, i = idx & 31;
    float freq = powf(10000.0f, (float)i * (1.0f / 32.0f));
    float ang  = (float)pos / freq;
    g_sincos[idx] = make_float2(sinf(ang), cosf(ang));
}

__global__ void copy_kernel(float4* __restrict__ dst, const float4* __restrict__ src, int n) {
    int i = blockIdx.x * blockDim.x + threadIdx.x;
    int stride = gridDim.x * blockDim.x;
    for (; i < n; i += stride) dst[i] = src[i];
}

// x (f32) -> g_xh (fp16); n = TOKENS*DMODEL/4
__global__ void cvtx_kernel(const float4* __restrict__ x, int n) {
    uint2* dst = reinterpret_cast<uint2*>(g_xh);
    int i = blockIdx.x * blockDim.x + threadIdx.x;
    int stride = gridDim.x * blockDim.x;
    for (; i < n; i += stride) {
        float4 v = x[i];
        __half2 h0 = __floats2half2_rn(v.x, v.y);
        __half2 h1 = __floats2half2_rn(v.z, v.w);
        dst[i] = make_uint2(h2_bits(h0), h2_bits(h1));
    }
}

// W[mat][head][k][nin] -> g_wh[(mat*16+head)*128 + nin][k], fp16
__global__ void wprep_kernel(const float* __restrict__ WQ,
                             const float* __restrict__ WK,
                             const float* __restrict__ WV) {
    __shared__ float t[32][33];
    int n0 = blockIdx.x * 32;     // 192 tiles over n
    int k0 = blockIdx.y * 32;     // 64 tiles over k
    int tx = threadIdx.x, ty = threadIdx.y;   // 32 x 8
#pragma unroll
    for (int j = 0; j < 4; j++) {
        int n = n0 + tx;
        int k = k0 + ty + j * 8;
        int mat = n >> 11;
        int rest = n & 2047;                 // head*128 + nin
        const float* W = (mat == 0) ? WQ : (mat == 1) ? WK : WV;
        t[ty + j * 8][tx] =
            W[(size_t)(rest >> 7) * DMODEL * DHEAD + (size_t)k * DHEAD + (rest & 127)];
    }
    __syncthreads();
#pragma unroll
    for (int j = 0; j < 4; j++) {
        int n = n0 + ty + j * 8;
        int k = k0 + tx;
        g_wh[(size_t)n * DMODEL + k] = __float2half_rn(t[tx][ty + j * 8]);
    }
}

// ---------------------------------------------------------------------------
// GEMM: gridDim = (48 [mat*16+head], 64 [M tiles]), 256 threads, 8 warps (4m x 2n)
// ---------------------------------------------------------------------------
__global__ void __launch_bounds__(256, 2)
qkv_gemm_kernel(const float* __restrict__ bQ, const float* __restrict__ bK,
                const float* __restrict__ bV, float* __restrict__ out) {
    extern __shared__ __half smem[];

    const int nb   = blockIdx.x;           // 0..47
    const int mb   = blockIdx.y;           // 0..63
    const int mat  = nb >> 4;              // 0=Q, 1=K, 2=V
    const int head = nb & 15;

    const __half* Ag = g_xh + (size_t)mb * BM * DMODEL;
    const __half* Bg = g_wh + (size_t)nb * BN * DMODEL;   // K-major [128 n][2048 k]
    const float* bsel = (mat == 0) ? bQ : (mat == 1) ? bK : bV;
    const float* bias = bsel + head * DHEAD;
    float* Og = out + (size_t)(mat + 1) * TOKENS * DMODEL + head * DHEAD;

    const bool do_rot = (mat < 2);         // rotary on Q/K only

    const int tid    = threadIdx.x;
    const int wid    = tid >> 5;
    const int lane   = tid & 31;
    const int warp_m = wid >> 1;           // 0..3 -> m offset *32
    const int warp_n = wid & 1;            // 0..1 -> n offset *64
    const int g      = lane >> 2;          // groupID
    const int c      = lane & 3;           // threadID_in_group

    float acc[2][8][4];
#pragma unroll
    for (int mi = 0; mi < 2; mi++)
#pragma unroll
        for (int ni = 0; ni < 8; ni++)
#pragma unroll
            for (int r = 0; r < 4; r++) acc[mi][ni][r] = 0.0f;

    // ---- stage loader: tiles [128 rows][64 k] fp16, stride LDH=72 halfs ----
    auto load_stage = [&](int buf, int k0) {
        __half* As = smem + buf * STAGE_H;
        __half* Bs = As + A_H;
#pragma unroll
        for (int i = 0; i < 4; i++) {          // A: 1024 x 16B segs
            int id = tid + i * 256;
            int r = id >> 3, s = id & 7;
            cp_async16(As + r * LDH + s * 8, Ag + (size_t)r * DMODEL + k0 + s * 8);
        }
#pragma unroll
        for (int i = 0; i < 4; i++) {          // B: 1024 x 16B segs
            int id = tid + i * 256;
            int r = id >> 3, s = id & 7;
            cp_async16(Bs + r * LDH + s * 8, Bg + (size_t)r * DMODEL + k0 + s * 8);
        }
        cp_commit();
    };

    const int KT = DMODEL / BK;   // 32
    load_stage(0, 0);             // group: stage 0
    load_stage(1, BK);            // group: stage 1

    for (int kt = 0; kt < KT; kt++) {
        // Two groups pending here (kt, kt+1) except at the tail; wait_group 1
        // leaves <=1 pending -> stage kt is complete. At the tail (kt=KT-1)
        // only stage kt is pending, so wait<0>.
        if (kt + 1 < KT) cp_wait<1>();
        else             cp_wait<0>();
        // Single barrier: (a) stage-kt smem data visible CTA-wide,
        // (b) every warp finished compute(kt-1) -> buffer (kt-1)%3 == (kt+2)%3 free.
        __syncthreads();
        if (kt + 2 < KT) load_stage((kt + 2) % NSTAGE, (kt + 2) * BK);

        // word view: row stride 36 uint32 (LDH/2)
        const uint32_t* Aw =
            reinterpret_cast<const uint32_t*>(smem + (kt % NSTAGE) * STAGE_H);
        const uint32_t* Bw = Aw + A_H / 2;

#pragma unroll
        for (int ks = 0; ks < 4; ks++) {       // four k16 steps per BK=64
            const int kw = ks * 8;             // 8 words = 16 halfs
            uint32_t a[2][4];
#pragma unroll
            for (int mi = 0; mi < 2; mi++) {
                int r0 = warp_m * 32 + mi * 16 + g;
                a[mi][0] = Aw[r0 * 36 + kw + c];
                a[mi][1] = Aw[(r0 + 8) * 36 + kw + c];
                a[mi][2] = Aw[r0 * 36 + kw + c + 4];
                a[mi][3] = Aw[(r0 + 8) * 36 + kw + c + 4];
            }
            uint32_t b[8][2];
#pragma unroll
            for (int ni = 0; ni < 8; ni++) {
                int n = warp_n * 64 + ni * 8 + g;       // B row (K-major)
                b[ni][0] = Bw[n * 36 + kw + c];
                b[ni][1] = Bw[n * 36 + kw + c + 4];
            }
#pragma unroll
            for (int mi = 0; mi < 2; mi++)
#pragma unroll
                for (int ni = 0; ni < 8; ni++)
                    mma_f16(acc[mi][ni], a[mi][0], a[mi][1], a[mi][2], a[mi][3],
                            b[ni][0], b[ni][1]);
        }
    }

    // ---- epilogue: bias + rotary(Q,K only) + store ----
#pragma unroll
    for (int mi = 0; mi < 2; mi++) {
#pragma unroll
        for (int half = 0; half < 2; half++) {   // rows g / g+8
            int row = mb * BM + warp_m * 32 + mi * 16 + g + half * 8;  // token
            int pos = row & (SEQLEN - 1);
            float* orow = Og + (size_t)row * DMODEL;
            const float2* sct = g_sincos + pos * 32;
            int r0 = half * 2;   // acc regs {0,1} or {2,3}
#pragma unroll
            for (int ni = 0; ni < 8; ni++) {
                int e = warp_n * 64 + ni * 8 + c * 2;   // even column in head
                float v0 = acc[mi][ni][r0]     + bias[e];
                float v1 = acc[mi][ni][r0 + 1] + bias[e + 1];
                if (do_rot && e < ROT_DIM) {
                    float2 sc = sct[e >> 1];   // x=sin, y=cos
                    float o0 = v0 * sc.y - v1 * sc.x;
                    float o1 = v1 * sc.y + v0 * sc.x;
                    v0 = o0; v1 = o1;
                }
                *reinterpret_cast<float2*>(orow + e) = make_float2(v0, v1);
            }
        }
    }
}

// ---------------------------------------------------------------------------
extern "C" void kernel_launch(void* const* d_in, const int* in_sizes, int n_in,
                              void* d_out, int out_size) {
    const float* residual = (const float*)d_in[0];
    const float* x        = (const float*)d_in[1];
    const float* WQ       = (const float*)d_in[2];
    const float* WK       = (const float*)d_in[3];
    const float* WV       = (const float*)d_in[4];
    const float* bQ       = (const float*)d_in[5];
    const float* bK       = (const float*)d_in[6];
    const float* bV       = (const float*)d_in[7];
    float* out = (float*)d_out;

    // residual passthrough: 4,194,304 float4
    copy_kernel<<<4096, 256>>>((float4*)out, (const float4*)residual,
                               (TOKENS * DMODEL) / 4);
    // prep: fp16 x, transposed fp16 W (K-major), rotary table
    cvtx_kernel<<<4096, 256>>>((const float4*)x, (TOKENS * DMODEL) / 4);
    wprep_kernel<<<dim3(NTOT / 32, DMODEL / 32), dim3(32, 8)>>>(WQ, WK, WV);
    sincos_kernel<<<256, 256>>>();

    // fused QKV GEMM + bias + rotary
    cudaFuncSetAttribute(qkv_gemm_kernel,
                         cudaFuncAttributeMaxDynamicSharedMemorySize, SMEM_BYTES);
    dim3 grid(48, 64);
    qkv_gemm_kernel<<<grid, 256, SMEM_BYTES>>>(bQ, bK, bV, out);
}